// round 11
// baseline (speedup 1.0000x reference)
#include <cuda_runtime.h>
#include <cstdint>

// h_t = tanh(x_t @ W_ih^T + b_ih + b_hh + h_{t-1} @ W_hh^T); out = h_{T-1}
// B=4096, T=512, IN=15, HID=20.
//
// ZERO-SMEM design: both x and h move between lanes via shfl64 (register
// exchange). No STS/LDS, no __syncwarp, no barriers of any kind — the shfl
// collectives are the only (and sufficient) synchronization.
// Warp = 3 batches, lane = (batch, hidden units 2tl,2tl+1), 1366 1-warp CTAs.
// Lane p<8 of each group keeps a depth-3 register FIFO of packed x-pairs.
// tanh via MUFU.TANH (tanh.approx.f32): 1 instr, 16cyc, ~2^-10.7 max rel err
// on the final step only (earlier errors contracted by the recurrence).

#define T_STEPS 512
#define BATCH   4096
#define N_IN    15
#define N_HID   20
#define BPW     3                      // batches per warp
#define THREADS 32
#define N_CTAS  ((BATCH + BPW - 1) / BPW)   // 1366
#define FULL    0xffffffffu

typedef unsigned long long ull;

__device__ __forceinline__ ull pack2(float lo, float hi) {
    ull r; asm("mov.b64 %0, {%1, %2};" : "=l"(r) : "f"(lo), "f"(hi)); return r;
}
__device__ __forceinline__ ull fma2(ull a, ull b, ull c) {
    ull d; asm("fma.rn.f32x2 %0, %1, %2, %3;" : "=l"(d) : "l"(a), "l"(b), "l"(c)); return d;
}
__device__ __forceinline__ ull add2(ull a, ull b) {
    ull d; asm("add.rn.f32x2 %0, %1, %2;" : "=l"(d) : "l"(a), "l"(b)); return d;
}
__device__ __forceinline__ float hsum2(ull a) {
    float lo, hi; asm("mov.b64 {%0, %1}, %2;" : "=f"(lo), "=f"(hi) : "l"(a));
    return lo + hi;
}
__device__ __forceinline__ float tanh_mufu(float z) {
    float r; asm("tanh.approx.f32 %0, %1;" : "=f"(r) : "f"(z)); return r;
}

__global__ __launch_bounds__(THREADS, 10)
void rnn_allreg_kernel(const float* __restrict__ feature,
                       const float* __restrict__ W_ih,
                       const float* __restrict__ W_hh,
                       const float* __restrict__ b_ih,
                       const float* __restrict__ b_hh,
                       float* __restrict__ out)
{
    const int lane = threadIdx.x & 31;
    const int g    = lane / 10;                  // 0..2 batch slot (3 = riders)
    const int tl   = lane % 10;
    const bool active = (g < BPW);
    const int  gc  = active ? g : 0;
    const int  base = gc * 10;                   // first lane of this group
    const int  b   = blockIdx.x * BPW + gc;      // < 4096 (1366*3 = 4098, last CTA: b<=4097)
    const bool valid = active && (b < BATCH);
    const int j0 = 2 * tl, j1 = 2 * tl + 1;

    // x-loader role: lane tl<8 supplies packed pair (x[2tl], x[2tl+1]) (pair7: x14,0)
    const bool xl  = valid && (tl < 8);
    const bool xhi = (tl < 7);                   // pair has a valid high element

    // ---- loop-invariant packed weights (f32x2 k-pairs) ----
    ull wx0[8], wx1[8], wh0[10], wh1[10];
#pragma unroll
    for (int p = 0; p < 7; p++) {
        wx0[p] = pack2(W_ih[j0 * N_IN + 2 * p], W_ih[j0 * N_IN + 2 * p + 1]);
        wx1[p] = pack2(W_ih[j1 * N_IN + 2 * p], W_ih[j1 * N_IN + 2 * p + 1]);
    }
    wx0[7] = pack2(W_ih[j0 * N_IN + 14], 0.0f);
    wx1[7] = pack2(W_ih[j1 * N_IN + 14], 0.0f);
#pragma unroll
    for (int p = 0; p < 10; p++) {
        wh0[p] = pack2(W_hh[j0 * N_HID + 2 * p], W_hh[j0 * N_HID + 2 * p + 1]);
        wh1[p] = pack2(W_hh[j1 * N_HID + 2 * p], W_hh[j1 * N_HID + 2 * p + 1]);
    }
    const ull bias2_0 = pack2(b_ih[j0] + b_hh[j0], 0.0f);
    const ull bias2_1 = pack2(b_ih[j1] + b_hh[j1], 0.0f);

    // ---- x pair FIFO in registers: cur = x_t pair, f1..f3 = x_{t+1..t+3} ----
    const float* xrow = feature + (size_t)(valid ? b : 0) * T_STEPS * N_IN;
    ull cur = 0, f1 = 0, f2 = 0, f3 = 0;
    if (xl) {
        cur = pack2(xrow[0 * N_IN + 2 * tl], xhi ? xrow[0 * N_IN + 2 * tl + 1] : 0.0f);
        f1  = pack2(xrow[1 * N_IN + 2 * tl], xhi ? xrow[1 * N_IN + 2 * tl + 1] : 0.0f);
        f2  = pack2(xrow[2 * N_IN + 2 * tl], xhi ? xrow[2 * N_IN + 2 * tl + 1] : 0.0f);
        f3  = pack2(xrow[3 * N_IN + 2 * tl], xhi ? xrow[3 * N_IN + 2 * tl + 1] : 0.0f);
    }

    ull hpk = 0ull;   // packed (h[2tl], h[2tl+1]) for this lane's units

#pragma unroll 2
    for (int t = 0; t < T_STEPS; t++) {
        // gather x_t pairs: 8x shfl64 from loader lanes (register exchange)
        ull xp[8];
#pragma unroll
        for (int p = 0; p < 8; p++)
            xp[p] = __shfl_sync(FULL, cur, base + p);

        // gather h_{t-1} pairs: 10x shfl64 (already packed, no pack instrs)
        ull hp[10];
#pragma unroll
        for (int s = 0; s < 10; s++)
            hp[s] = __shfl_sync(FULL, hpk, base + s);

        // advance FIFO; prefetch x_{t+4} (2x LDG.32, loader lanes only)
        cur = f1; f1 = f2; f2 = f3;
        if (xl && (t + 4) < T_STEPS) {
            const float* r4 = xrow + (t + 4) * N_IN + 2 * tl;
            f3 = pack2(r4[0], xhi ? r4[1] : 0.0f);
        } else {
            f3 = 0ull;
        }

        // 36 fma2 over 4 chains (depth ~9 each)
        ull a0 = bias2_0, c0 = 0ull, a1 = bias2_1, c1 = 0ull;
#pragma unroll
        for (int k = 0; k < 8; k++) {
            if (k & 1) { c0 = fma2(xp[k], wx0[k], c0); c1 = fma2(xp[k], wx1[k], c1); }
            else       { a0 = fma2(xp[k], wx0[k], a0); a1 = fma2(xp[k], wx1[k], a1); }
        }
#pragma unroll
        for (int k = 0; k < 10; k++) {
            if (k & 1) { c0 = fma2(hp[k], wh0[k], c0); c1 = fma2(hp[k], wh1[k], c1); }
            else       { a0 = fma2(hp[k], wh0[k], a0); a1 = fma2(hp[k], wh1[k], a1); }
        }
        const float z0 = hsum2(add2(a0, c0));
        const float z1 = hsum2(add2(a1, c1));

        // MUFU.TANH: single instruction, stays off the long-latency exp path
        hpk = pack2(tanh_mufu(z0), tanh_mufu(z1));
    }

    if (valid) {
        float lo, hi;
        asm("mov.b64 {%0, %1}, %2;" : "=f"(lo), "=f"(hi) : "l"(hpk));
        *(float2*)&out[b * N_HID + j0] = make_float2(lo, hi);  // 8B-aligned STG.64
    }
}

extern "C" void kernel_launch(void* const* d_in, const int* in_sizes, int n_in,
                              void* d_out, int out_size)
{
    const float* feature = (const float*)d_in[0];
    const float* W_ih    = (const float*)d_in[1];
    const float* W_hh    = (const float*)d_in[2];
    const float* b_ih    = (const float*)d_in[3];
    const float* b_hh    = (const float*)d_in[4];
    float* out = (float*)d_out;

    rnn_allreg_kernel<<<N_CTAS, THREADS>>>(feature, W_ih, W_hh, b_ih, b_hh, out);
}